// round 1
// baseline (speedup 1.0000x reference)
#include <cuda_runtime.h>

#define NN 100000
#define NE 1600000
#define NQ 400000
#define NB_SCAN 98   // ceil(100000/1024)

// ---------------- scratch (static device globals; no runtime alloc) ---------
__device__ int   g_counts[NN];
__device__ int   g_rowptr[NN];
__device__ int   g_wptr[NN];
__device__ float g_dinv[NN];
__device__ int   g_csrs[NE];
__device__ float g_csrw[NE];
__device__ float g_agg[(size_t)NN * 128];
__device__ int   g_bsum[NB_SCAN];
__device__ int   g_boff[NB_SCAN];

// ---------------- small utility kernels -------------------------------------
__global__ void k_zero_counts() {
    int i = blockIdx.x * blockDim.x + threadIdx.x;
    if (i < NN) g_counts[i] = 0;
}

__global__ void k_count(const int* __restrict__ dst) {
    int e = blockIdx.x * blockDim.x + threadIdx.x;
    if (e < NE) atomicAdd(&g_counts[dst[e]], 1);
}

__global__ void k_dinv() {
    int i = blockIdx.x * blockDim.x + threadIdx.x;
    if (i < NN) g_dinv[i] = rsqrtf((float)g_counts[i] + 1.0f);
}

// exclusive scan of g_counts -> g_rowptr, per 1024-chunk, chunk totals to g_bsum
__global__ void k_scan_partial() {
    __shared__ int sh[1024];
    int t = threadIdx.x;
    int i = blockIdx.x * 1024 + t;
    int v = (i < NN) ? g_counts[i] : 0;
    sh[t] = v;
    __syncthreads();
#pragma unroll
    for (int off = 1; off < 1024; off <<= 1) {
        int add = (t >= off) ? sh[t - off] : 0;
        __syncthreads();
        sh[t] += add;
        __syncthreads();
    }
    if (i < NN) g_rowptr[i] = sh[t] - v;   // exclusive
    if (t == 1023) g_bsum[blockIdx.x] = sh[1023];
}

__global__ void k_scan_block() {
    __shared__ int sh[128];
    int t = threadIdx.x;
    int v = (t < NB_SCAN) ? g_bsum[t] : 0;
    sh[t] = v;
    __syncthreads();
#pragma unroll
    for (int off = 1; off < 128; off <<= 1) {
        int add = (t >= off) ? sh[t - off] : 0;
        __syncthreads();
        sh[t] += add;
        __syncthreads();
    }
    if (t < NB_SCAN) g_boff[t] = sh[t] - v;   // exclusive
}

__global__ void k_scan_add() {
    int i = blockIdx.x * 1024 + threadIdx.x;
    if (i < NN) {
        int r = g_rowptr[i] + g_boff[blockIdx.x];
        g_rowptr[i] = r;
        g_wptr[i]   = r;
    }
}

__global__ void k_scatter(const int* __restrict__ src, const int* __restrict__ dst) {
    int e = blockIdx.x * blockDim.x + threadIdx.x;
    if (e < NE) {
        int d = dst[e];
        int s = src[e];
        int pos = atomicAdd(&g_wptr[d], 1);
        g_csrs[pos] = s;
        g_csrw[pos] = g_dinv[s];
    }
}

// ---------------- aggregation: one warp per node, 128 feats (float4/lane) ---
__global__ void k_agg(const float4* __restrict__ table, float4* __restrict__ out) {
    int w    = (blockIdx.x * blockDim.x + threadIdx.x) >> 5;
    int lane = threadIdx.x & 31;
    if (w >= NN) return;
    int start = g_rowptr[w];
    int cnt   = g_counts[w];
    float4 acc = make_float4(0.f, 0.f, 0.f, 0.f);
    for (int i = 0; i < cnt; i++) {
        int   s  = g_csrs[start + i];
        float wt = g_csrw[start + i];
        float4 v = table[(size_t)s * 32 + lane];
        acc.x += wt * v.x; acc.y += wt * v.y;
        acc.z += wt * v.z; acc.w += wt * v.w;
    }
    float  di = g_dinv[w];
    float4 sv = table[(size_t)w * 32 + lane];
    acc.x = di * (acc.x + di * sv.x);
    acc.y = di * (acc.y + di * sv.y);
    acc.z = di * (acc.z + di * sv.z);
    acc.w = di * (acc.w + di * sv.w);
    out[(size_t)w * 32 + lane] = acc;
}

// ---------------- fp32 GEMM: C[M,N] = A[M,128] @ W[128,N] + bias (opt relu) -
// BM=128, BN=128, BK=16, 256 threads, 8x8 microtile
template <bool RELU>
__global__ __launch_bounds__(256)
void k_gemm(const float* __restrict__ A, const float* __restrict__ W,
            const float* __restrict__ bias, float* __restrict__ C,
            int M, int N) {
    __shared__ float As[16][128];
    __shared__ float Ws[16][128];
    int tid = threadIdx.x;
    int bm  = blockIdx.x * 128;
    int bn  = blockIdx.y * 128;
    int ty  = tid >> 4;      // 0..15 -> rows ty*8..+7
    int tx  = tid & 15;      // 0..15 -> cols tx*8..+7

    float acc[8][8];
#pragma unroll
    for (int i = 0; i < 8; i++)
#pragma unroll
        for (int j = 0; j < 8; j++) acc[i][j] = 0.f;

    for (int k0 = 0; k0 < 128; k0 += 16) {
        if (k0) __syncthreads();
        // A tile: 128 rows x 16 k -> store transposed As[k][m]
#pragma unroll
        for (int half = 0; half < 2; half++) {
            int f   = tid + half * 256;        // 0..511
            int row = f >> 2;                  // 0..127
            int kq  = f & 3;                   // 0..3 -> k offset kq*4
            int gm  = bm + row;
            float4 a = make_float4(0.f, 0.f, 0.f, 0.f);
            if (gm < M) a = *(const float4*)&A[(size_t)gm * 128 + k0 + kq * 4];
            As[kq * 4 + 0][row] = a.x;
            As[kq * 4 + 1][row] = a.y;
            As[kq * 4 + 2][row] = a.z;
            As[kq * 4 + 3][row] = a.w;
        }
        // W tile: 16 k x 128 n, direct layout
#pragma unroll
        for (int half = 0; half < 2; half++) {
            int f    = tid + half * 256;       // 0..511
            int krow = f >> 5;                 // 0..15
            int nq   = f & 31;                 // 0..31 -> n offset nq*4
            float4 w = *(const float4*)&W[(size_t)(k0 + krow) * N + bn + nq * 4];
            *(float4*)&Ws[krow][nq * 4] = w;
        }
        __syncthreads();
#pragma unroll
        for (int kk = 0; kk < 16; kk++) {
            float4 a0 = *(const float4*)&As[kk][ty * 8];
            float4 a1 = *(const float4*)&As[kk][ty * 8 + 4];
            float4 b0 = *(const float4*)&Ws[kk][tx * 8];
            float4 b1 = *(const float4*)&Ws[kk][tx * 8 + 4];
            float a[8] = {a0.x, a0.y, a0.z, a0.w, a1.x, a1.y, a1.z, a1.w};
            float b[8] = {b0.x, b0.y, b0.z, b0.w, b1.x, b1.y, b1.z, b1.w};
#pragma unroll
            for (int i = 0; i < 8; i++)
#pragma unroll
                for (int j = 0; j < 8; j++) acc[i][j] += a[i] * b[j];
        }
    }

    // epilogue
    float bv[8];
#pragma unroll
    for (int j = 0; j < 8; j++) bv[j] = bias[bn + tx * 8 + j];
#pragma unroll
    for (int i = 0; i < 8; i++) {
        int m = bm + ty * 8 + i;
        if (m >= M) continue;
        float4 c0, c1;
        c0.x = acc[i][0] + bv[0]; c0.y = acc[i][1] + bv[1];
        c0.z = acc[i][2] + bv[2]; c0.w = acc[i][3] + bv[3];
        c1.x = acc[i][4] + bv[4]; c1.y = acc[i][5] + bv[5];
        c1.z = acc[i][6] + bv[6]; c1.w = acc[i][7] + bv[7];
        if (RELU) {
            c0.x = fmaxf(c0.x, 0.f); c0.y = fmaxf(c0.y, 0.f);
            c0.z = fmaxf(c0.z, 0.f); c0.w = fmaxf(c0.w, 0.f);
            c1.x = fmaxf(c1.x, 0.f); c1.y = fmaxf(c1.y, 0.f);
            c1.z = fmaxf(c1.z, 0.f); c1.w = fmaxf(c1.w, 0.f);
        }
        float* cp = &C[(size_t)m * N + bn + tx * 8];
        *(float4*)cp       = c0;
        *(float4*)(cp + 4) = c1;
    }
}

// ---------------- query: warp per q-edge, 2 heads of 64 feats ---------------
__global__ void k_query(const int* __restrict__ qrow, const int* __restrict__ qcol,
                        const int* __restrict__ y, const float* __restrict__ emb,
                        float* __restrict__ pi, float* __restrict__ pj,
                        float* __restrict__ pr) {
    int e    = (blockIdx.x * blockDim.x + threadIdx.x) >> 5;
    int lane = threadIdx.x & 31;
    if (e >= NQ) return;
    int r  = qrow[e], c = qcol[e];
    int hr = y[r],    hc = y[c];
    const float2* er = (const float2*)(emb + (size_t)r * 512);
    const float2* ec = (const float2*)(emb + (size_t)c * 512);

    float2 a0 = er[hr * 32 + lane];
    float2 b0 = ec[hr * 32 + lane];
    float si = a0.x * b0.x + a0.y * b0.y;
    float2 a1 = er[hc * 32 + lane];
    float2 b1 = ec[hc * 32 + lane];
    float sj = a1.x * b1.x + a1.y * b1.y;
#pragma unroll
    for (int off = 16; off; off >>= 1) {
        si += __shfl_xor_sync(0xFFFFFFFFu, si, off);
        sj += __shfl_xor_sync(0xFFFFFFFFu, sj, off);
    }
    if (lane == 0) {
        pi[e] = si;
        pj[e] = sj;
        pr[e] = 0.5f * (si + sj);
    }
}

// ---------------- launch ----------------------------------------------------
extern "C" void kernel_launch(void* const* d_in, const int* in_sizes, int n_in,
                              void* d_out, int out_size) {
    const float* x  = (const float*)d_in[0];
    const float* W1 = (const float*)d_in[1];
    const float* b1 = (const float*)d_in[2];
    const float* W2 = (const float*)d_in[3];
    const float* b2 = (const float*)d_in[4];
    const int*   ei = (const int*)d_in[5];
    const int*   qi = (const int*)d_in[6];
    const int*   y  = (const int*)d_in[7];

    const int* src = ei;
    const int* dst = ei + NE;
    const int* qr  = qi;
    const int* qc  = qi + NQ;

    float* out     = (float*)d_out;
    float* hiddens = out;                         // [100000,128]
    float* emb     = out + 12800000;              // [100000,512]
    float* pi      = out + 64000000;              // [400000]
    float* pj      = out + 64400000;              // [400000]
    float* pr      = out + 64800000;              // [400000]

    void* aggp = nullptr;
    cudaGetSymbolAddress(&aggp, g_agg);
    float* agg = (float*)aggp;

    // CSR build
    k_zero_counts<<<(NN + 255) / 256, 256>>>();
    k_count<<<(NE + 255) / 256, 256>>>(dst);
    k_dinv<<<(NN + 255) / 256, 256>>>();
    k_scan_partial<<<NB_SCAN, 1024>>>();
    k_scan_block<<<1, 128>>>();
    k_scan_add<<<NB_SCAN, 1024>>>();
    k_scatter<<<(NE + 255) / 256, 256>>>(src, dst);

    // layer 1: agg(x) @ W1 + b1, relu
    k_agg<<<(NN * 32 + 255) / 256, 256>>>((const float4*)x, (float4*)agg);
    {
        dim3 grid((NN + 127) / 128, 1);
        k_gemm<true><<<grid, 256>>>(agg, W1, b1, hiddens, NN, 128);
    }

    // layer 2: agg(hiddens) @ W2 + b2
    k_agg<<<(NN * 32 + 255) / 256, 256>>>((const float4*)hiddens, (float4*)agg);
    {
        dim3 grid((NN + 127) / 128, 4);
        k_gemm<false><<<grid, 256>>>(agg, W2, b2, emb, NN, 512);
    }

    // queries
    k_query<<<(NQ * 32 + 255) / 256, 256>>>(qr, qc, y, emb, pi, pj, pr);
}

// round 3
// speedup vs baseline: 1.4578x; 1.4578x over previous
#include <cuda_runtime.h>

#define NN 100000
#define NE 1600000
#define NQ 400000
#define NB_SCAN 98   // ceil(100000/1024)

// ---------------- scratch (static device globals; no runtime alloc) ---------
__device__ int   g_counts[NN];
__device__ int   g_rowptr[NN];
__device__ int   g_wptr[NN];
__device__ float g_dinv[NN];
__device__ int   g_csrs[NE];
__device__ float g_csrw[NE];
__device__ float g_agg[(size_t)NN * 128];
__device__ int   g_bsum[NB_SCAN];
__device__ int   g_boff[NB_SCAN];

// ---------------- small utility kernels -------------------------------------
__global__ void k_zero_counts() {
    int i = blockIdx.x * blockDim.x + threadIdx.x;
    if (i < NN) g_counts[i] = 0;
}

__global__ void k_count(const int* __restrict__ dst) {
    int e = blockIdx.x * blockDim.x + threadIdx.x;
    if (e < NE) atomicAdd(&g_counts[dst[e]], 1);
}

__global__ void k_dinv() {
    int i = blockIdx.x * blockDim.x + threadIdx.x;
    if (i < NN) g_dinv[i] = rsqrtf((float)g_counts[i] + 1.0f);
}

// exclusive scan of g_counts -> g_rowptr, per 1024-chunk, chunk totals to g_bsum
__global__ void k_scan_partial() {
    __shared__ int sh[1024];
    int t = threadIdx.x;
    int i = blockIdx.x * 1024 + t;
    int v = (i < NN) ? g_counts[i] : 0;
    sh[t] = v;
    __syncthreads();
#pragma unroll
    for (int off = 1; off < 1024; off <<= 1) {
        int add = (t >= off) ? sh[t - off] : 0;
        __syncthreads();
        sh[t] += add;
        __syncthreads();
    }
    if (i < NN) g_rowptr[i] = sh[t] - v;   // exclusive
    if (t == 1023) g_bsum[blockIdx.x] = sh[1023];
}

__global__ void k_scan_block() {
    __shared__ int sh[128];
    int t = threadIdx.x;
    int v = (t < NB_SCAN) ? g_bsum[t] : 0;
    sh[t] = v;
    __syncthreads();
#pragma unroll
    for (int off = 1; off < 128; off <<= 1) {
        int add = (t >= off) ? sh[t - off] : 0;
        __syncthreads();
        sh[t] += add;
        __syncthreads();
    }
    if (t < NB_SCAN) g_boff[t] = sh[t] - v;   // exclusive
}

__global__ void k_scan_add() {
    int i = blockIdx.x * 1024 + threadIdx.x;
    if (i < NN) {
        int r = g_rowptr[i] + g_boff[blockIdx.x];
        g_rowptr[i] = r;
        g_wptr[i]   = r;
    }
}

__global__ void k_scatter(const int* __restrict__ src, const int* __restrict__ dst) {
    int e = blockIdx.x * blockDim.x + threadIdx.x;
    if (e < NE) {
        int d = dst[e];
        int s = src[e];
        int pos = atomicAdd(&g_wptr[d], 1);
        g_csrs[pos] = s;
        g_csrw[pos] = g_dinv[s];
    }
}

// ---------------- aggregation: one warp per node, 128 feats (float4/lane) ---
__global__ void k_agg(const float4* __restrict__ table, float4* __restrict__ out) {
    int w    = (blockIdx.x * blockDim.x + threadIdx.x) >> 5;
    int lane = threadIdx.x & 31;
    if (w >= NN) return;
    int start = g_rowptr[w];
    int cnt   = g_counts[w];
    float4 acc = make_float4(0.f, 0.f, 0.f, 0.f);
    for (int i = 0; i < cnt; i++) {
        int   s  = g_csrs[start + i];
        float wt = g_csrw[start + i];
        float4 v = table[(size_t)s * 32 + lane];
        acc.x += wt * v.x; acc.y += wt * v.y;
        acc.z += wt * v.z; acc.w += wt * v.w;
    }
    float  di = g_dinv[w];
    float4 sv = table[(size_t)w * 32 + lane];
    acc.x = di * (acc.x + di * sv.x);
    acc.y = di * (acc.y + di * sv.y);
    acc.z = di * (acc.z + di * sv.z);
    acc.w = di * (acc.w + di * sv.w);
    out[(size_t)w * 32 + lane] = acc;
}

// ---------------- tf32 tensor-core GEMM -------------------------------------
// C[M,N] = A[M,128] @ W[128,N] + bias (opt relu)
// BM=128, BN=128, BK=32, 256 threads (8 warps as 2x4), warp tile 64x32
__device__ __forceinline__ unsigned f2tf32(float x) {
    unsigned u;
    asm("cvt.rna.tf32.f32 %0, %1;" : "=r"(u) : "f"(x));
    return u;
}

__device__ __forceinline__ void mma_tf32(
    float& d0, float& d1, float& d2, float& d3,
    unsigned a0, unsigned a1, unsigned a2, unsigned a3,
    unsigned b0, unsigned b1)
{
    asm volatile(
        "mma.sync.aligned.m16n8k8.row.col.f32.tf32.tf32.f32 "
        "{%0,%1,%2,%3}, {%4,%5,%6,%7}, {%8,%9}, {%0,%1,%2,%3};"
        : "+f"(d0), "+f"(d1), "+f"(d2), "+f"(d3)
        : "r"(a0), "r"(a1), "r"(a2), "r"(a3), "r"(b0), "r"(b1));
}

template <bool RELU>
__global__ __launch_bounds__(256)
void k_gemm_tf32(const float* __restrict__ A, const float* __restrict__ W,
                 const float* __restrict__ bias, float* __restrict__ C,
                 int M, int N) {
    __shared__ unsigned As[32][132];   // [k][m], tf32 bits
    __shared__ unsigned Ws[32][132];   // [k][n], tf32 bits

    int tid  = threadIdx.x;
    int bm   = blockIdx.x * 128;
    int bn   = blockIdx.y * 128;
    int warp = tid >> 5;
    int lane = tid & 31;
    int g    = lane >> 2;        // group id (0..7)
    int c    = lane & 3;         // thread in group (0..3)
    int wm   = (warp & 1) * 64;  // warp M offset
    int wn   = (warp >> 1) * 32; // warp N offset

    float acc[4][4][4];          // [mfrag][nfrag][reg]
#pragma unroll
    for (int i = 0; i < 4; i++)
#pragma unroll
        for (int j = 0; j < 4; j++)
#pragma unroll
            for (int r = 0; r < 4; r++) acc[i][j][r] = 0.f;

    for (int k0 = 0; k0 < 128; k0 += 32) {
        if (k0) __syncthreads();
        // A tile: 128 rows x 32 k -> As[k][m] (transposed), tf32-converted
#pragma unroll
        for (int it = 0; it < 4; it++) {
            int slot = tid + it * 256;       // 0..1023 float4 slots
            int row  = slot >> 3;            // 0..127
            int kq   = slot & 7;             // 0..7 -> k offset kq*4
            int gm   = bm + row;
            float4 a = make_float4(0.f, 0.f, 0.f, 0.f);
            if (gm < M) a = *(const float4*)&A[(size_t)gm * 128 + k0 + kq * 4];
            As[kq * 4 + 0][row] = f2tf32(a.x);
            As[kq * 4 + 1][row] = f2tf32(a.y);
            As[kq * 4 + 2][row] = f2tf32(a.z);
            As[kq * 4 + 3][row] = f2tf32(a.w);
        }
        // W tile: 32 k x 128 n -> Ws[k][n], tf32-converted
#pragma unroll
        for (int it = 0; it < 4; it++) {
            int slot = tid + it * 256;       // 0..1023
            int krow = slot >> 5;            // 0..31
            int nq   = slot & 31;            // 0..31 -> n offset nq*4
            float4 w = *(const float4*)&W[(size_t)(k0 + krow) * N + bn + nq * 4];
            Ws[krow][nq * 4 + 0] = f2tf32(w.x);
            Ws[krow][nq * 4 + 1] = f2tf32(w.y);
            Ws[krow][nq * 4 + 2] = f2tf32(w.z);
            Ws[krow][nq * 4 + 3] = f2tf32(w.w);
        }
        __syncthreads();

#pragma unroll
        for (int kk = 0; kk < 32; kk += 8) {
            unsigned af[4][4];
#pragma unroll
            for (int mf = 0; mf < 4; mf++) {
                int m = wm + mf * 16 + g;
                af[mf][0] = As[kk + c][m];
                af[mf][1] = As[kk + c][m + 8];
                af[mf][2] = As[kk + c + 4][m];
                af[mf][3] = As[kk + c + 4][m + 8];
            }
            unsigned bf[4][2];
#pragma unroll
            for (int nf = 0; nf < 4; nf++) {
                int n = wn + nf * 8 + g;
                bf[nf][0] = Ws[kk + c][n];
                bf[nf][1] = Ws[kk + c + 4][n];
            }
#pragma unroll
            for (int mf = 0; mf < 4; mf++)
#pragma unroll
                for (int nf = 0; nf < 4; nf++)
                    mma_tf32(acc[mf][nf][0], acc[mf][nf][1],
                             acc[mf][nf][2], acc[mf][nf][3],
                             af[mf][0], af[mf][1], af[mf][2], af[mf][3],
                             bf[nf][0], bf[nf][1]);
        }
    }

    // epilogue: c0=C[g][2c], c1=C[g][2c+1], c2=C[g+8][2c], c3=C[g+8][2c+1]
#pragma unroll
    for (int nf = 0; nf < 4; nf++) {
        int nc = bn + wn + nf * 8 + 2 * c;
        float bx = bias[nc], by = bias[nc + 1];
#pragma unroll
        for (int mf = 0; mf < 4; mf++) {
            int m0 = bm + wm + mf * 16 + g;
            float v0 = acc[mf][nf][0] + bx;
            float v1 = acc[mf][nf][1] + by;
            float v2 = acc[mf][nf][2] + bx;
            float v3 = acc[mf][nf][3] + by;
            if (RELU) {
                v0 = fmaxf(v0, 0.f); v1 = fmaxf(v1, 0.f);
                v2 = fmaxf(v2, 0.f); v3 = fmaxf(v3, 0.f);
            }
            if (m0 < M)     *(float2*)&C[(size_t)m0 * N + nc]       = make_float2(v0, v1);
            if (m0 + 8 < M) *(float2*)&C[(size_t)(m0 + 8) * N + nc] = make_float2(v2, v3);
        }
    }
}

// ---------------- query: warp per q-edge, 2 heads of 64 feats ---------------
__global__ void k_query(const int* __restrict__ qrow, const int* __restrict__ qcol,
                        const int* __restrict__ y, const float* __restrict__ emb,
                        float* __restrict__ pi, float* __restrict__ pj,
                        float* __restrict__ pr) {
    int e    = (blockIdx.x * blockDim.x + threadIdx.x) >> 5;
    int lane = threadIdx.x & 31;
    if (e >= NQ) return;
    int r  = qrow[e], c = qcol[e];
    int hr = y[r],    hc = y[c];
    const float2* er = (const float2*)(emb + (size_t)r * 512);
    const float2* ec = (const float2*)(emb + (size_t)c * 512);

    float2 a0 = er[hr * 32 + lane];
    float2 b0 = ec[hr * 32 + lane];
    float si = a0.x * b0.x + a0.y * b0.y;
    float2 a1 = er[hc * 32 + lane];
    float2 b1 = ec[hc * 32 + lane];
    float sj = a1.x * b1.x + a1.y * b1.y;
#pragma unroll
    for (int off = 16; off; off >>= 1) {
        si += __shfl_xor_sync(0xFFFFFFFFu, si, off);
        sj += __shfl_xor_sync(0xFFFFFFFFu, sj, off);
    }
    if (lane == 0) {
        pi[e] = si;
        pj[e] = sj;
        pr[e] = 0.5f * (si + sj);
    }
}

// ---------------- launch ----------------------------------------------------
extern "C" void kernel_launch(void* const* d_in, const int* in_sizes, int n_in,
                              void* d_out, int out_size) {
    const float* x  = (const float*)d_in[0];
    const float* W1 = (const float*)d_in[1];
    const float* b1 = (const float*)d_in[2];
    const float* W2 = (const float*)d_in[3];
    const float* b2 = (const float*)d_in[4];
    const int*   ei = (const int*)d_in[5];
    const int*   qi = (const int*)d_in[6];
    const int*   y  = (const int*)d_in[7];

    const int* src = ei;
    const int* dst = ei + NE;
    const int* qr  = qi;
    const int* qc  = qi + NQ;

    float* out     = (float*)d_out;
    float* hiddens = out;                         // [100000,128]
    float* emb     = out + 12800000;              // [100000,512]
    float* pi      = out + 64000000;              // [400000]
    float* pj      = out + 64400000;              // [400000]
    float* pr      = out + 64800000;              // [400000]

    void* aggp = nullptr;
    cudaGetSymbolAddress(&aggp, g_agg);
    float* agg = (float*)aggp;

    // CSR build
    k_zero_counts<<<(NN + 255) / 256, 256>>>();
    k_count<<<(NE + 255) / 256, 256>>>(dst);
    k_dinv<<<(NN + 255) / 256, 256>>>();
    k_scan_partial<<<NB_SCAN, 1024>>>();
    k_scan_block<<<1, 128>>>();
    k_scan_add<<<NB_SCAN, 1024>>>();
    k_scatter<<<(NE + 255) / 256, 256>>>(src, dst);

    // layer 1: agg(x) @ W1 + b1, relu
    k_agg<<<(NN * 32 + 255) / 256, 256>>>((const float4*)x, (float4*)agg);
    {
        dim3 grid((NN + 127) / 128, 1);
        k_gemm_tf32<true><<<grid, 256>>>(agg, W1, b1, hiddens, NN, 128);
    }

    // layer 2: agg(hiddens) @ W2 + b2
    k_agg<<<(NN * 32 + 255) / 256, 256>>>((const float4*)hiddens, (float4*)agg);
    {
        dim3 grid((NN + 127) / 128, 4);
        k_gemm_tf32<false><<<grid, 256>>>(agg, W2, b2, emb, NN, 512);
    }

    // queries
    k_query<<<(NQ * 32 + 255) / 256, 256>>>(qr, qc, y, emb, pi, pj, pr);
}